// round 7
// baseline (speedup 1.0000x reference)
#include <cuda_runtime.h>
#include <cuda_bf16.h>
#include <cstdint>

// SAN Subtraction: out[n,c,k,l] = x[n,c,oh,ow] - x[n,c, refl(oh+i-3), refl(ow+j-3)]
//   x: [8, 64, 56, 56] fp32, K=7, pad=3 reflect;  out: [8, 64, 49, 3136] fp32.
//
// R6: TMA bulk-store the 315 MB write stream.
//  - Half-plane CTAs (28 rows), 128 thr, grid=1024. Pre-reflected padded
//    input tile in smem (34 x 88-stride, conflict-free LDS.128) as before.
//  - i-outer loop: compute the 7 j-slices for kernel-row i into 7 smem
//    staging buffers (6272 B each, contiguous per k-slice in gmem), then
//    cp.async.bulk shared->global per slice: DRAM gets 6.3 KB sequential
//    bursts instead of 50K interleaved 512 B streams -> row-buffer hits,
//    deep fire-and-forget write pipeline independent of warp count.
//  - wait_group.read recycles staging after the SMEM reads only (~350 cyc),
//    not after the DRAM drain.

#define H 56
#define W 56
#define PLANE (H * W)      // 3136
#define KK 49
#define RPC 28             // output rows per CTA (half plane)
#define SROWS 34           // RPC + 6 halo
#define PCOLS 62
#define RS 88              // padded tile row stride (floats)
#define SLICE_FLOATS (RPC * W)          // 1568
#define SLICE_BYTES (SLICE_FLOATS * 4)  // 6272
#define NP (RPC * (W / 4))              // 392 float4 positions per half

__global__ __launch_bounds__(128, 4)
void san_subtraction_kernel(const float* __restrict__ x,
                            float* __restrict__ out) {
    __shared__ __align__(16) float sp[SROWS * RS];         // 11.97 KB
    __shared__ __align__(16) float stage[7 * SLICE_FLOATS]; // 43.9 KB

    const int plane = blockIdx.x >> 1;
    const int half  = blockIdx.x & 1;
    const int r0    = half * RPC;

    const float* __restrict__ xin = x + (size_t)plane * PLANE;

    // Stage pre-reflected padded tile: rows r0-3 .. r0+30, cols -3 .. 58.
    // refl(p) = min(|p|, 110-|p|)
    for (int t = threadIdx.x; t < SROWS * PCOLS; t += 128) {
        const int lr = t / PCOLS;
        const int pc = t - lr * PCOLS;
        int g = r0 + lr - 3;
        g = g < 0 ? -g : g;
        g = g < 110 - g ? g : 110 - g;
        int w = pc - 3;
        w = w < 0 ? -w : w;
        w = w < 110 - w ? w : 110 - w;
        sp[lr * RS + pc] = xin[g * W + w];
    }
    __syncthreads();

    // gmem base of this half's k-slices: slice k is SLICE_BYTES contiguous.
    float* __restrict__ ob0 =
        out + (size_t)plane * KK * PLANE + (size_t)r0 * W;

    uint32_t stage_addr;
    {
        uint64_t tmp;
        asm("cvta.to.shared.u64 %0, %1;" : "=l"(tmp) : "l"(stage));
        stage_addr = (uint32_t)tmp;
    }

#pragma unroll
    for (int i = 0; i < 7; ++i) {
        // Compute the 7 j-slices for kernel-row i into staging.
        for (int pos = threadIdx.x; pos < NP; pos += 128) {
            const int lrow = pos / 14;
            const int w0   = (pos - lrow * 14) * 4;

            // Center cols w0..w0+3 = padded cols w0+3..w0+6 of row lrow+3.
            float4 center;
            {
                const float4* cp =
                    reinterpret_cast<const float4*>(sp + (lrow + 3) * RS + w0);
                const float4 A = cp[0], B = cp[1];
                center = make_float4(A.w, B.x, B.y, B.z);
            }

            const float4* p =
                reinterpret_cast<const float4*>(sp + (lrow + i) * RS + w0);
            const float4 A = p[0], B = p[1], C = p[2];
            const float vv[12] = {A.x, A.y, A.z, A.w,
                                  B.x, B.y, B.z, B.w,
                                  C.x, C.y, C.z, C.w};

            float* st = stage + pos * 4;  // in-slice offset == lrow*W + w0
#pragma unroll
            for (int j = 0; j < 7; ++j) {
                float4 r;
                r.x = center.x - vv[j];
                r.y = center.y - vv[j + 1];
                r.z = center.z - vv[j + 2];
                r.w = center.w - vv[j + 3];
                // lanes consecutive -> 512B conflict-free STS.128 groups
                *reinterpret_cast<float4*>(st + j * SLICE_FLOATS) = r;
            }
        }
        __syncthreads();  // all STS visible before async-proxy reads

        if (threadIdx.x == 0) {
            asm volatile("fence.proxy.async.shared::cta;" ::: "memory");
#pragma unroll
            for (int j = 0; j < 7; ++j) {
                float* dst = ob0 + (size_t)(i * 7 + j) * PLANE;
                asm volatile(
                    "cp.async.bulk.global.shared::cta.bulk_group [%0], [%1], %2;"
                    :: "l"(dst),
                       "r"(stage_addr + j * SLICE_BYTES),
                       "n"(SLICE_BYTES)
                    : "memory");
            }
            asm volatile("cp.async.bulk.commit_group;" ::: "memory");
            // Recycle staging once SMEM reads complete (writes drain async).
            asm volatile("cp.async.bulk.wait_group.read 0;" ::: "memory");
        }
        __syncthreads();  // staging free for next i
    }
}

extern "C" void kernel_launch(void* const* d_in, const int* in_sizes, int n_in,
                              void* d_out, int out_size) {
    const float* x = (const float*)d_in[0];
    float* out = (float*)d_out;
    const int planes = in_sizes[0] / PLANE;  // 512
    san_subtraction_kernel<<<planes * 2, 128>>>(x, out);
}